// round 2
// baseline (speedup 1.0000x reference)
#include <cuda_runtime.h>
#include <cuda_bf16.h>
#include <math.h>

// Problem constants
#define BB 128      // batch
#define LL 64       // encoder length
#define HH 512      // hidden
#define WORD 512
#define VOCAB 32000
#define TSTEPS 31   // T-1 decode steps

// ---------------- scratch (device globals; no allocation allowed) --------
__device__ float g_encproj[BB*LL*HH];     // 16 MB  enc @ W1_enc^T (step-invariant)
__device__ float g_a1[BB*LL*HH];          // 16 MB
__device__ float g_a2[BB*LL*HH];          // 16 MB
__device__ float g_hidproj[BB*HH];
__device__ float g_e[BB*LL];
__device__ float g_ctx[BB*HH];
__device__ float g_xcat[BB*(WORD+HH)];
__device__ float g_gi[BB*3*HH];
__device__ float g_gh[BB*3*HH];
__device__ float g_hid0[BB*HH];
__device__ float g_hid1[BB*HH];
__device__ float g_logits[BB*VOCAB];      // 16 MB

// ---------------- generic SGEMM: C[M,N] = act(A[M,K] @ W[N,K]^T + bias) --
// A row-major stride lda, W row-major stride ldw (weight layout = x @ W.T)
template<int BM,int BN,int BK,int TM,int TN,int ACT>
__global__ __launch_bounds__(256)
void sgemm_wt(int M,int N,int K,
              const float* __restrict__ A,int lda,
              const float* __restrict__ W,int ldw,
              const float* __restrict__ bias,
              float* __restrict__ C,int ldc)
{
    __shared__ float As[BK][BM];
    __shared__ float Ws[BK][BN];
    const int bm = blockIdx.y*BM, bn = blockIdx.x*BN;
    const int tid = threadIdx.x;
    constexpr int TCOL = BN/TN;
    const int tr = (tid / TCOL)*TM;
    const int tc = (tid % TCOL)*TN;
    float acc[TM][TN];
#pragma unroll
    for (int i=0;i<TM;i++)
#pragma unroll
        for (int j=0;j<TN;j++) acc[i][j]=0.f;

    constexpr int KV = BK/4;                  // float4 chunks per row of the tile
    for (int k0=0;k0<K;k0+=BK) {
#pragma unroll
        for (int f = tid; f < BM*KV; f += 256) {
            int m = f / KV, k4 = (f % KV)*4;
            float4 v = *reinterpret_cast<const float4*>(&A[(size_t)(bm+m)*lda + k0 + k4]);
            As[k4+0][m]=v.x; As[k4+1][m]=v.y; As[k4+2][m]=v.z; As[k4+3][m]=v.w;
        }
#pragma unroll
        for (int f = tid; f < BN*KV; f += 256) {
            int n = f / KV, k4 = (f % KV)*4;
            float4 v = *reinterpret_cast<const float4*>(&W[(size_t)(bn+n)*ldw + k0 + k4]);
            Ws[k4+0][n]=v.x; Ws[k4+1][n]=v.y; Ws[k4+2][n]=v.z; Ws[k4+3][n]=v.w;
        }
        __syncthreads();
#pragma unroll
        for (int k=0;k<BK;k++) {
            float a[TM], w[TN];
#pragma unroll
            for (int i=0;i<TM;i+=4) {
                float4 v=*reinterpret_cast<const float4*>(&As[k][tr+i]);
                a[i]=v.x; a[i+1]=v.y; a[i+2]=v.z; a[i+3]=v.w;
            }
#pragma unroll
            for (int j=0;j<TN;j+=4) {
                float4 v=*reinterpret_cast<const float4*>(&Ws[k][tc+j]);
                w[j]=v.x; w[j+1]=v.y; w[j+2]=v.z; w[j+3]=v.w;
            }
#pragma unroll
            for (int i=0;i<TM;i++)
#pragma unroll
                for (int j=0;j<TN;j++) acc[i][j] = fmaf(a[i],w[j],acc[i][j]);
        }
        __syncthreads();
    }
#pragma unroll
    for (int i=0;i<TM;i++) {
#pragma unroll
        for (int j=0;j<TN;j++) {
            float v = acc[i][j] + (bias ? bias[bn+tc+j] : 0.f);
            if (ACT==1) v = tanhf(v);
            C[(size_t)(bm+tr+i)*ldc + bn+tc+j] = v;
        }
    }
}

// ---------------- small helpers ------------------------------------------
__global__ void copy_f32(const float* __restrict__ src, float* __restrict__ dst, int n){
    int i = blockIdx.x*256 + threadIdx.x;
    if (i < n) dst[i] = src[i];
}

// a1 = tanh(encproj[b,l,h] + hidproj[b,h])
__global__ void add_tanh_k(const float* __restrict__ encproj,
                           const float* __restrict__ hidproj,
                           float* __restrict__ a1){
    size_t idx = (size_t)blockIdx.x*256 + threadIdx.x;    // BB*LL*HH = 4194304
    int h   = (int)(idx & (HH-1));
    int row = (int)(idx >> 9);
    int b   = row >> 6;                                    // row / LL
    a1[idx] = tanhf(encproj[idx] + hidproj[b*HH + h]);
}

// e[row] = dot(a3[row,:], v)   (one warp per row)
__global__ void att_score_k(const float* __restrict__ a3,
                            const float* __restrict__ v,
                            float* __restrict__ e){
    int row = blockIdx.x*8 + threadIdx.y;                  // blockDim (32,8)
    const float* p = a3 + (size_t)row*HH;
    float s = 0.f;
    for (int h = threadIdx.x; h < HH; h += 32) s = fmaf(p[h], v[h], s);
#pragma unroll
    for (int o=16;o;o>>=1) s += __shfl_xor_sync(0xffffffffu, s, o);
    if (threadIdx.x==0) e[row] = s;
}

// softmax over L then ctx[b,h] = sum_l alpha[l]*enc[b,l,h]
__global__ void softmax_ctx_k(const float* __restrict__ e,
                              const float* __restrict__ enc,
                              float* __restrict__ ctx){
    int b = blockIdx.x, tid = threadIdx.x;
    __shared__ float alpha[LL];
    if (tid==0) {
        float m = -INFINITY;
        for (int l=0;l<LL;l++) m = fmaxf(m, e[b*LL+l]);
        float s = 0.f;
        for (int l=0;l<LL;l++){ float x = expf(e[b*LL+l]-m); alpha[l]=x; s+=x; }
        float inv = 1.f/s;
        for (int l=0;l<LL;l++) alpha[l]*=inv;
    }
    __syncthreads();
    const float* eb = enc + (size_t)b*LL*HH;
    for (int h=tid; h<HH; h+=blockDim.x) {
        float s = 0.f;
#pragma unroll 8
        for (int l=0;l<LL;l++) s = fmaf(alpha[l], eb[l*HH+h], s);
        ctx[b*HH+h] = s;
    }
}

// xcat = [embed_W[targets[b,t]], ctx[b]]
// NOTE: targets is int32 (JAX default x64-disabled downcasts jnp.int64 -> int32).
__global__ void build_xcat_k(const int* __restrict__ targets, int t,
                             const float* __restrict__ embed,
                             const float* __restrict__ ctx,
                             float* __restrict__ xcat){
    int b = blockIdx.x, tid = threadIdx.x;
    int tok = targets[b*32 + t];
    if (tok < 0) tok = 0;
    if (tok >= VOCAB) tok = VOCAB-1;          // defensive clamp (no-op if dtype correct)
    const float* er = embed + (size_t)tok*WORD;
    for (int h=tid; h<WORD+HH; h+=blockDim.x)
        xcat[b*(WORD+HH)+h] = (h<WORD) ? er[h] : ctx[b*HH + (h-WORD)];
}

// GRU gates -> hid_new
__global__ void gru_gate_k(const float* __restrict__ gi, const float* __restrict__ gh,
                           const float* __restrict__ hid, float* __restrict__ hidn){
    int idx = blockIdx.x*256 + threadIdx.x;   // BB*HH
    int b = idx >> 9, h = idx & (HH-1);
    const float* gib = gi + (size_t)b*3*HH;
    const float* ghb = gh + (size_t)b*3*HH;
    float r = 1.f/(1.f+expf(-(gib[h]        + ghb[h])));
    float z = 1.f/(1.f+expf(-(gib[HH+h]     + ghb[HH+h])));
    float n = tanhf(gib[2*HH+h] + r*ghb[2*HH+h]);
    hidn[idx] = (1.f-z)*n + z*hid[idx];
}

// log_softmax over VOCAB -> out (out already offset by t; per-b stride = TSTEPS*VOCAB)
__global__ __launch_bounds__(1024)
void log_softmax_k(const float* __restrict__ logits, float* __restrict__ out){
    int b = blockIdx.x, tid = threadIdx.x;
    const float* p = logits + (size_t)b*VOCAB;
    float* o = out + (size_t)b*TSTEPS*VOCAB;
    __shared__ float red[32];
    float m = -INFINITY;
    for (int v=tid; v<VOCAB; v+=1024) m = fmaxf(m, p[v]);
#pragma unroll
    for (int x=16;x;x>>=1) m = fmaxf(m, __shfl_xor_sync(0xffffffffu, m, x));
    if ((tid&31)==0) red[tid>>5] = m;
    __syncthreads();
    if (tid<32){ float mm = red[tid];
#pragma unroll
        for (int x=16;x;x>>=1) mm = fmaxf(mm, __shfl_xor_sync(0xffffffffu, mm, x));
        red[tid]=mm; }
    __syncthreads();
    m = red[0];
    __syncthreads();
    float s = 0.f;
    for (int v=tid; v<VOCAB; v+=1024) s += expf(p[v]-m);
#pragma unroll
    for (int x=16;x;x>>=1) s += __shfl_xor_sync(0xffffffffu, s, x);
    if ((tid&31)==0) red[tid>>5] = s;
    __syncthreads();
    if (tid<32){ float ss = red[tid];
#pragma unroll
        for (int x=16;x;x>>=1) ss += __shfl_xor_sync(0xffffffffu, ss, x);
        red[tid]=ss; }
    __syncthreads();
    float lse = m + logf(red[0]);
    for (int v=tid; v<VOCAB; v+=1024) o[v] = p[v] - lse;
}

// ---------------- host side ----------------------------------------------
static float* symaddr_checked(const void* sym){
    void* p = nullptr;
    cudaError_t e = cudaGetSymbolAddress(&p, sym);
    if (e != cudaSuccess) p = nullptr;
    return (float*)p;
}

extern "C" void kernel_launch(void* const* d_in, const int* in_sizes, int n_in,
                              void* d_out, int out_size) {
    const float* enc   = (const float*)d_in[0];   // (128,64,512)
    const float* h0    = (const float*)d_in[1];   // (1,128,512)
    const int*   tgt   = (const int*)d_in[2];     // (128,32) int32
    const float* embed = (const float*)d_in[3];
    const float* W1    = (const float*)d_in[4];   // (512,1024)
    const float* b1    = (const float*)d_in[5];
    const float* W2    = (const float*)d_in[6];
    const float* b2    = (const float*)d_in[7];
    const float* W3    = (const float*)d_in[8];
    const float* b3    = (const float*)d_in[9];
    const float* attv  = (const float*)d_in[10];
    const float* Wih   = (const float*)d_in[11];  // (1536,1024)
    const float* Whh   = (const float*)d_in[12];  // (1536,512)
    const float* bih   = (const float*)d_in[13];
    const float* bhh   = (const float*)d_in[14];
    const float* outW  = (const float*)d_in[15];  // (32000,512)
    const float* outb  = (const float*)d_in[16];
    float* out = (float*)d_out;

    static float* encproj = nullptr;
    static float* a1 = nullptr; static float* a2 = nullptr;
    static float* hidproj = nullptr; static float* ebuf = nullptr;
    static float* ctx = nullptr; static float* xcat = nullptr;
    static float* gi = nullptr; static float* gh = nullptr;
    static float* hidA = nullptr; static float* hidB = nullptr;
    static float* logits = nullptr;
    if (!encproj) {
        encproj = symaddr_checked(g_encproj);
        a1      = symaddr_checked(g_a1);
        a2      = symaddr_checked(g_a2);
        hidproj = symaddr_checked(g_hidproj);
        ebuf    = symaddr_checked(g_e);
        ctx     = symaddr_checked(g_ctx);
        xcat    = symaddr_checked(g_xcat);
        gi      = symaddr_checked(g_gi);
        gh      = symaddr_checked(g_gh);
        hidA    = symaddr_checked(g_hid0);
        hidB    = symaddr_checked(g_hid1);
        logits  = symaddr_checked(g_logits);
    }
    float* hid[2] = { hidA, hidB };

    const int M = BB*LL;  // 8192

    // hid <- encoder_hidden[0]
    copy_f32<<<(BB*HH+255)/256,256>>>(h0, hid[0], BB*HH);

    // Step-invariant: encproj = enc @ W1[:, :512]^T   (no bias, no act)
    sgemm_wt<128,128,8,8,8,0><<<dim3(HH/128, M/128), 256>>>(
        M, HH, HH, enc, HH, W1, 2*HH, nullptr, encproj, HH);

    for (int t = 0; t < TSTEPS; t++) {
        const float* hc = hid[t & 1];
        float*       hn = hid[(t+1) & 1];

        // hidproj = hid @ W1[:, 512:]^T + b1
        sgemm_wt<64,64,16,4,4,0><<<dim3(HH/64, BB/64), 256>>>(
            BB, HH, HH, hc, HH, W1 + HH, 2*HH, b1, hidproj, HH);

        // a1 = tanh(encproj + hidproj)
        add_tanh_k<<<(M*HH)/256, 256>>>(encproj, hidproj, a1);

        // a2 = tanh(a1 @ W2^T + b2)
        sgemm_wt<128,128,8,8,8,1><<<dim3(HH/128, M/128), 256>>>(
            M, HH, HH, a1, HH, W2, HH, b2, a2, HH);

        // a3 = tanh(a2 @ W3^T + b3)   (into a1)
        sgemm_wt<128,128,8,8,8,1><<<dim3(HH/128, M/128), 256>>>(
            M, HH, HH, a2, HH, W3, HH, b3, a1, HH);

        // e = a3 . v
        att_score_k<<<M/8, dim3(32,8)>>>(a1, attv, ebuf);

        // softmax + context
        softmax_ctx_k<<<BB, 256>>>(ebuf, enc, ctx);

        // xcat = [embed[target], ctx]
        build_xcat_k<<<BB, 256>>>(tgt, t, embed, ctx, xcat);

        // gi = xcat @ Wih^T + bih ; gh = hid @ Whh^T + bhh
        sgemm_wt<64,64,16,4,4,0><<<dim3(3*HH/64, BB/64), 256>>>(
            BB, 3*HH, WORD+HH, xcat, WORD+HH, Wih, WORD+HH, bih, gi, 3*HH);
        sgemm_wt<64,64,16,4,4,0><<<dim3(3*HH/64, BB/64), 256>>>(
            BB, 3*HH, HH, hc, HH, Whh, HH, bhh, gh, 3*HH);

        // GRU gates -> hid_new
        gru_gate_k<<<(BB*HH)/256, 256>>>(gi, gh, hc, hn);

        // logits = hid_new @ outW^T + outb
        sgemm_wt<128,128,8,8,8,0><<<dim3(VOCAB/128, BB/128), 256>>>(
            BB, VOCAB, HH, hn, HH, outW, HH, outb, logits, VOCAB);

        // log_softmax -> out[b, t, :]
        log_softmax_k<<<BB, 1024>>>(logits, out + (size_t)t*VOCAB);
    }
}

// round 3
// speedup vs baseline: 3.1225x; 3.1225x over previous
#include <cuda_runtime.h>
#include <cuda_bf16.h>
#include <math.h>
#include <stdint.h>

#define BB 128      // batch
#define LL 64       // encoder length
#define HH 512      // hidden
#define WORD 512
#define VOCAB 32000
#define TSTEPS 31   // T-1 decode steps

typedef __nv_bfloat16  bf16;
typedef __nv_bfloat162 bf162;

// ---------------- scratch (device globals; no allocation allowed) --------
// fp32
__device__ float g_encproj[BB*LL*HH];     // enc @ W1_enc^T (step-invariant)
__device__ float g_hidproj[BB*HH];
__device__ float g_e[BB*LL];
__device__ float g_ctx[BB*HH];
__device__ float g_gi[BB*3*HH];
__device__ float g_gh[BB*3*HH];
__device__ float g_hid0[BB*HH];
__device__ float g_hid1[BB*HH];
__device__ float g_logits[BB*VOCAB];
// bf16
__device__ bf16 g_encbf [BB*LL*HH];
__device__ bf16 g_w1l   [HH*HH];
__device__ bf16 g_w1h   [HH*HH];
__device__ bf16 g_w2    [HH*HH];
__device__ bf16 g_w3    [HH*HH];
__device__ bf16 g_wih   [3*HH*(WORD+HH)];
__device__ bf16 g_whh   [3*HH*HH];
__device__ bf16 g_outw  [VOCAB*HH];
__device__ bf16 g_a2bf  [BB*LL*HH];
__device__ bf16 g_a3bf  [BB*LL*HH];
__device__ bf16 g_xcatbf[BB*(WORD+HH)];
__device__ bf16 g_hbf0  [BB*HH];
__device__ bf16 g_hbf1  [BB*HH];

// ---------------- mma helpers --------------------------------------------
__device__ __forceinline__ uint32_t s2u(const void* p){
    return (uint32_t)__cvta_generic_to_shared(p);
}
__device__ __forceinline__ void ldsm4(uint32_t& a0,uint32_t& a1,uint32_t& a2,uint32_t& a3,uint32_t addr){
    asm volatile("ldmatrix.sync.aligned.m8n8.x4.shared.b16 {%0,%1,%2,%3},[%4];"
                 :"=r"(a0),"=r"(a1),"=r"(a2),"=r"(a3):"r"(addr));
}
__device__ __forceinline__ void ldsm2(uint32_t& b0,uint32_t& b1,uint32_t addr){
    asm volatile("ldmatrix.sync.aligned.m8n8.x2.shared.b16 {%0,%1},[%2];"
                 :"=r"(b0),"=r"(b1):"r"(addr));
}
__device__ __forceinline__ void mma16816(float* c,const uint32_t* a,const uint32_t* b){
    asm volatile("mma.sync.aligned.m16n8k16.row.col.f32.bf16.bf16.f32 "
                 "{%0,%1,%2,%3},{%4,%5,%6,%7},{%8,%9},{%0,%1,%2,%3};"
                 :"+f"(c[0]),"+f"(c[1]),"+f"(c[2]),"+f"(c[3])
                 :"r"(a[0]),"r"(a[1]),"r"(a[2]),"r"(a[3]),"r"(b[0]),"r"(b[1]));
}

// ---------------- bf16 tensor-core GEMM ----------------------------------
// C[M,N] = act(A[M,K] @ W[N,K]^T + bias)
// MODE_A: 0 = A is bf16[M,lda]; 1 = A = tanh(encproj_fp32[row,:] + hidproj[row>>6,:]) (fused)
// ACT:    1 = tanh epilogue
// OUT_BF: 1 = C bf16, 0 = C fp32
// Block tile 128x128xK, BK=32, 256 threads (8 warps as 2x4, warp tile 64x32).
#define BK 32
#define SPAD 8
template<int MODE_A,int ACT,int OUT_BF>
__global__ __launch_bounds__(256)
void bgemm(int M,int N,int K,
           const void* __restrict__ Aptr,int lda,
           const float* __restrict__ hidproj,
           const bf16* __restrict__ Wbf,int ldw,
           const float* __restrict__ bias,
           void* __restrict__ Cptr,int ldc)
{
    __shared__ bf16 As[128][BK+SPAD];
    __shared__ bf16 Ws[128][BK+SPAD];
    const int bm = blockIdx.y*128, bn = blockIdx.x*128;
    const int tid = threadIdx.x, lane = tid & 31, wid = tid >> 5;
    const int wm = wid & 1, wn = wid >> 1;

    float acc[4][4][4];
#pragma unroll
    for(int mi=0;mi<4;mi++)
#pragma unroll
        for(int ni=0;ni<4;ni++)
#pragma unroll
            for(int q=0;q<4;q++) acc[mi][ni][q]=0.f;

    for(int k0=0;k0<K;k0+=BK){
        // --- stage A tile (128 x 32) ---
        if(MODE_A==0){
            const bf16* Ab=(const bf16*)Aptr;
#pragma unroll
            for(int it=0;it<2;it++){
                int f=tid+it*256, r=f>>2, kq=(f&3)*8;
                *(uint4*)&As[r][kq] =
                    *(const uint4*)&Ab[(size_t)(bm+r)*lda + k0 + kq];
            }
        } else {
            const float* Af=(const float*)Aptr;
#pragma unroll
            for(int it=0;it<2;it++){
                int f=tid+it*256, r=f>>2, kq=(f&3)*8;
                int row=bm+r, b=row>>6;
                const float* ep=&Af[(size_t)row*lda + k0 + kq];
                const float* hp=&hidproj[b*HH + k0 + kq];
                float4 e0=*(const float4*)ep,      e1=*(const float4*)(ep+4);
                float4 h0=*(const float4*)hp,      h1=*(const float4*)(hp+4);
                union{ uint4 u; bf162 h[4]; } pk;
                pk.h[0]=__floats2bfloat162_rn(tanhf(e0.x+h0.x), tanhf(e0.y+h0.y));
                pk.h[1]=__floats2bfloat162_rn(tanhf(e0.z+h0.z), tanhf(e0.w+h0.w));
                pk.h[2]=__floats2bfloat162_rn(tanhf(e1.x+h1.x), tanhf(e1.y+h1.y));
                pk.h[3]=__floats2bfloat162_rn(tanhf(e1.z+h1.z), tanhf(e1.w+h1.w));
                *(uint4*)&As[r][kq] = pk.u;
            }
        }
        // --- stage W tile (128 x 32) ---
#pragma unroll
        for(int it=0;it<2;it++){
            int f=tid+it*256, r=f>>2, kq=(f&3)*8;
            *(uint4*)&Ws[r][kq] =
                *(const uint4*)&Wbf[(size_t)(bn+r)*ldw + k0 + kq];
        }
        __syncthreads();

#pragma unroll
        for(int ks=0;ks<2;ks++){
            uint32_t af[4][4], bw[4][2];
#pragma unroll
            for(int mi=0;mi<4;mi++)
                ldsm4(af[mi][0],af[mi][1],af[mi][2],af[mi][3],
                      s2u(&As[wm*64+mi*16 + (lane&15)][ks*16 + (lane>>4)*8]));
#pragma unroll
            for(int ni=0;ni<4;ni++)
                ldsm2(bw[ni][0],bw[ni][1],
                      s2u(&Ws[wn*32+ni*8 + (lane&7)][ks*16 + ((lane>>3)&1)*8]));
#pragma unroll
            for(int mi=0;mi<4;mi++)
#pragma unroll
                for(int ni=0;ni<4;ni++) mma16816(acc[mi][ni],af[mi],bw[ni]);
        }
        __syncthreads();
    }

    // --- epilogue ---
#pragma unroll
    for(int mi=0;mi<4;mi++){
#pragma unroll
        for(int ni=0;ni<4;ni++){
            int row = bm + wm*64 + mi*16 + (lane>>2);
            int col = bn + wn*32 + ni*8  + (lane&3)*2;
#pragma unroll
            for(int half=0;half<2;half++){
                int r2 = row + half*8;
                float v0 = acc[mi][ni][2*half+0];
                float v1 = acc[mi][ni][2*half+1];
                if(bias){ v0 += bias[col]; v1 += bias[col+1]; }
                if(ACT){ v0 = tanhf(v0); v1 = tanhf(v1); }
                if(OUT_BF){
                    ((bf162*)Cptr)[((size_t)r2*ldc + col)>>1] = __floats2bfloat162_rn(v0,v1);
                } else {
                    *(float2*)&((float*)Cptr)[(size_t)r2*ldc + col] = make_float2(v0,v1);
                }
            }
        }
    }
}

// ---------------- small helpers ------------------------------------------
__global__ void copy_f32(const float* __restrict__ src, float* __restrict__ dst, int n){
    int i = blockIdx.x*256 + threadIdx.x;
    if (i < n) dst[i] = src[i];
}
// fp32 (strided 2-D) -> bf16 (dense)
__global__ void cvt2d_k(const float* __restrict__ src, int lds, int cols,
                        bf16* __restrict__ dst, long long n){
    long long i = (long long)blockIdx.x*256 + threadIdx.x;
    if (i >= n) return;
    long long r = i / cols; int c = (int)(i - r*cols);
    dst[i] = __float2bfloat16(src[r*(long long)lds + c]);
}

// e[row] = dot(a3[row,:], v)   (one warp per row; a3 bf16)
__global__ void att_score_k(const bf16* __restrict__ a3,
                            const float* __restrict__ v,
                            float* __restrict__ e){
    int row = blockIdx.x*8 + threadIdx.y;
    const bf16* p = a3 + (size_t)row*HH;
    float s = 0.f;
    for (int h = threadIdx.x; h < HH; h += 32) s = fmaf(__bfloat162float(p[h]), v[h], s);
#pragma unroll
    for (int o=16;o;o>>=1) s += __shfl_xor_sync(0xffffffffu, s, o);
    if (threadIdx.x==0) e[row] = s;
}

// softmax over L then ctx[b,h] = sum_l alpha[l]*enc[b,l,h]
__global__ void softmax_ctx_k(const float* __restrict__ e,
                              const float* __restrict__ enc,
                              float* __restrict__ ctx){
    int b = blockIdx.x, tid = threadIdx.x;
    __shared__ float alpha[LL];
    if (tid==0) {
        float m = -INFINITY;
        for (int l=0;l<LL;l++) m = fmaxf(m, e[b*LL+l]);
        float s = 0.f;
        for (int l=0;l<LL;l++){ float x = expf(e[b*LL+l]-m); alpha[l]=x; s+=x; }
        float inv = 1.f/s;
        for (int l=0;l<LL;l++) alpha[l]*=inv;
    }
    __syncthreads();
    const float* eb = enc + (size_t)b*LL*HH;
    for (int h=tid; h<HH; h+=blockDim.x) {
        float s = 0.f;
#pragma unroll 8
        for (int l=0;l<LL;l++) s = fmaf(alpha[l], eb[l*HH+h], s);
        ctx[b*HH+h] = s;
    }
}

// xcat(bf16) = [embed_W[targets[b,t]], ctx[b]]   (targets int32)
__global__ void build_xcat_k(const int* __restrict__ targets, int t,
                             const float* __restrict__ embed,
                             const float* __restrict__ ctx,
                             bf16* __restrict__ xcat){
    int b = blockIdx.x, tid = threadIdx.x;
    int tok = targets[b*32 + t];
    if (tok < 0) tok = 0;
    if (tok >= VOCAB) tok = VOCAB-1;
    const float* er = embed + (size_t)tok*WORD;
    for (int h=tid; h<WORD+HH; h+=blockDim.x){
        float v = (h<WORD) ? er[h] : ctx[b*HH + (h-WORD)];
        xcat[b*(WORD+HH)+h] = __float2bfloat16(v);
    }
}

// GRU gates -> hid_new (fp32 + bf16 copy)
__global__ void gru_gate_k(const float* __restrict__ gi, const float* __restrict__ gh,
                           const float* __restrict__ hid,
                           float* __restrict__ hidn, bf16* __restrict__ hidnbf){
    int idx = blockIdx.x*256 + threadIdx.x;   // BB*HH
    int b = idx >> 9, h = idx & (HH-1);
    const float* gib = gi + (size_t)b*3*HH;
    const float* ghb = gh + (size_t)b*3*HH;
    float r = 1.f/(1.f+expf(-(gib[h]        + ghb[h])));
    float z = 1.f/(1.f+expf(-(gib[HH+h]     + ghb[HH+h])));
    float n = tanhf(gib[2*HH+h] + r*ghb[2*HH+h]);
    float hv = (1.f-z)*n + z*hid[idx];
    hidn[idx] = hv;
    hidnbf[idx] = __float2bfloat16(hv);
}

// log_softmax over VOCAB -> out (out already offset by t; per-b stride = TSTEPS*VOCAB)
__global__ __launch_bounds__(1024)
void log_softmax_k(const float* __restrict__ logits, float* __restrict__ out){
    int b = blockIdx.x, tid = threadIdx.x;
    const float* p = logits + (size_t)b*VOCAB;
    float* o = out + (size_t)b*TSTEPS*VOCAB;
    __shared__ float red[32];
    float m = -INFINITY;
    for (int v=tid; v<VOCAB; v+=1024) m = fmaxf(m, p[v]);
#pragma unroll
    for (int x=16;x;x>>=1) m = fmaxf(m, __shfl_xor_sync(0xffffffffu, m, x));
    if ((tid&31)==0) red[tid>>5] = m;
    __syncthreads();
    if (tid<32){ float mm = red[tid];
#pragma unroll
        for (int x=16;x;x>>=1) mm = fmaxf(mm, __shfl_xor_sync(0xffffffffu, mm, x));
        red[tid]=mm; }
    __syncthreads();
    m = red[0];
    __syncthreads();
    float s = 0.f;
    for (int v=tid; v<VOCAB; v+=1024) s += expf(p[v]-m);
#pragma unroll
    for (int x=16;x;x>>=1) s += __shfl_xor_sync(0xffffffffu, s, x);
    if ((tid&31)==0) red[tid>>5] = s;
    __syncthreads();
    if (tid<32){ float ss = red[tid];
#pragma unroll
        for (int x=16;x;x>>=1) ss += __shfl_xor_sync(0xffffffffu, ss, x);
        red[tid]=ss; }
    __syncthreads();
    float lse = m + logf(red[0]);
    for (int v=tid; v<VOCAB; v+=1024) o[v] = p[v] - lse;
}

// ---------------- host side ----------------------------------------------
static void* symaddr_checked(const void* sym){
    void* p = nullptr;
    if (cudaGetSymbolAddress(&p, sym) != cudaSuccess) p = nullptr;
    return p;
}

extern "C" void kernel_launch(void* const* d_in, const int* in_sizes, int n_in,
                              void* d_out, int out_size) {
    const float* enc   = (const float*)d_in[0];   // (128,64,512)
    const float* h0    = (const float*)d_in[1];   // (1,128,512)
    const int*   tgt   = (const int*)d_in[2];     // (128,32) int32
    const float* embed = (const float*)d_in[3];
    const float* W1    = (const float*)d_in[4];   // (512,1024)
    const float* b1    = (const float*)d_in[5];
    const float* W2    = (const float*)d_in[6];
    const float* b2    = (const float*)d_in[7];
    const float* W3    = (const float*)d_in[8];
    const float* b3    = (const float*)d_in[9];
    const float* attv  = (const float*)d_in[10];
    const float* Wih   = (const float*)d_in[11];  // (1536,1024)
    const float* Whh   = (const float*)d_in[12];  // (1536,512)
    const float* bih   = (const float*)d_in[13];
    const float* bhh   = (const float*)d_in[14];
    const float* outW  = (const float*)d_in[15];  // (32000,512)
    const float* outb  = (const float*)d_in[16];
    float* out = (float*)d_out;

    static float *encproj=nullptr,*hidproj,*ebuf,*ctx,*gi,*gh,*hidA,*hidB,*logits;
    static bf16  *encbf,*w1l,*w1h,*w2,*w3,*wih,*whh,*outw,*a2bf,*a3bf,*xcatbf,*hbfA,*hbfB;
    if (!encproj) {
        encproj=(float*)symaddr_checked(g_encproj);
        hidproj=(float*)symaddr_checked(g_hidproj);
        ebuf   =(float*)symaddr_checked(g_e);
        ctx    =(float*)symaddr_checked(g_ctx);
        gi     =(float*)symaddr_checked(g_gi);
        gh     =(float*)symaddr_checked(g_gh);
        hidA   =(float*)symaddr_checked(g_hid0);
        hidB   =(float*)symaddr_checked(g_hid1);
        logits =(float*)symaddr_checked(g_logits);
        encbf  =(bf16*)symaddr_checked(g_encbf);
        w1l    =(bf16*)symaddr_checked(g_w1l);
        w1h    =(bf16*)symaddr_checked(g_w1h);
        w2     =(bf16*)symaddr_checked(g_w2);
        w3     =(bf16*)symaddr_checked(g_w3);
        wih    =(bf16*)symaddr_checked(g_wih);
        whh    =(bf16*)symaddr_checked(g_whh);
        outw   =(bf16*)symaddr_checked(g_outw);
        a2bf   =(bf16*)symaddr_checked(g_a2bf);
        a3bf   =(bf16*)symaddr_checked(g_a3bf);
        xcatbf =(bf16*)symaddr_checked(g_xcatbf);
        hbfA   =(bf16*)symaddr_checked(g_hbf0);
        hbfB   =(bf16*)symaddr_checked(g_hbf1);
    }
    float* hid[2] = { hidA, hidB };
    bf16*  hbf[2] = { hbfA, hbfB };

    const int M = BB*LL;  // 8192
    auto blks = [](long long n){ return (int)((n + 255)/256); };

    // ---- one-time per launch: conversions + invariant GEMM ----
    copy_f32<<<blks(BB*HH),256>>>(h0, hid[0], BB*HH);
    cvt2d_k<<<blks(BB*HH),256>>>(h0, HH, HH, hbf[0], (long long)BB*HH);
    cvt2d_k<<<blks((long long)M*HH),256>>>(enc, HH, HH, encbf, (long long)M*HH);
    cvt2d_k<<<blks(HH*HH),256>>>(W1,      2*HH, HH, w1l, (long long)HH*HH);
    cvt2d_k<<<blks(HH*HH),256>>>(W1+HH,   2*HH, HH, w1h, (long long)HH*HH);
    cvt2d_k<<<blks(HH*HH),256>>>(W2,      HH,   HH, w2,  (long long)HH*HH);
    cvt2d_k<<<blks(HH*HH),256>>>(W3,      HH,   HH, w3,  (long long)HH*HH);
    cvt2d_k<<<blks((long long)3*HH*(WORD+HH)),256>>>(Wih, WORD+HH, WORD+HH, wih, (long long)3*HH*(WORD+HH));
    cvt2d_k<<<blks((long long)3*HH*HH),256>>>(Whh, HH, HH, whh, (long long)3*HH*HH);
    cvt2d_k<<<blks((long long)VOCAB*HH),256>>>(outW, HH, HH, outw, (long long)VOCAB*HH);

    // encproj = enc @ W1_enc^T  (no bias/act; fp32 out)
    bgemm<0,0,0><<<dim3(HH/128, M/128), 256>>>(
        M, HH, HH, encbf, HH, nullptr, w1l, HH, nullptr, encproj, HH);

    for (int t = 0; t < TSTEPS; t++) {
        const float* hc  = hid[t & 1];
        float*       hn  = hid[(t+1) & 1];
        const bf16*  hbc = hbf[t & 1];
        bf16*        hbn = hbf[(t+1) & 1];

        // hidproj = hid @ W1_hid^T + b1   (fp32 out)
        bgemm<0,0,0><<<dim3(HH/128, 1), 256>>>(
            BB, HH, HH, hbc, HH, nullptr, w1h, HH, b1, hidproj, HH);

        // a2 = tanh( tanh(encproj + hidproj) @ W2^T + b2 )   (fused A, bf16 out)
        bgemm<1,1,1><<<dim3(HH/128, M/128), 256>>>(
            M, HH, HH, encproj, HH, hidproj, w2, HH, b2, a2bf, HH);

        // a3 = tanh(a2 @ W3^T + b3)   (bf16 out)
        bgemm<0,1,1><<<dim3(HH/128, M/128), 256>>>(
            M, HH, HH, a2bf, HH, nullptr, w3, HH, b3, a3bf, HH);

        // e = a3 . v ; softmax + context ; xcat
        att_score_k<<<M/8, dim3(32,8)>>>(a3bf, attv, ebuf);
        softmax_ctx_k<<<BB, 256>>>(ebuf, enc, ctx);
        build_xcat_k<<<BB, 256>>>(tgt, t, embed, ctx, xcatbf);

        // gi = xcat @ Wih^T + bih ; gh = hid @ Whh^T + bhh   (fp32 out)
        bgemm<0,0,0><<<dim3(3*HH/128, 1), 256>>>(
            BB, 3*HH, WORD+HH, xcatbf, WORD+HH, nullptr, wih, WORD+HH, bih, gi, 3*HH);
        bgemm<0,0,0><<<dim3(3*HH/128, 1), 256>>>(
            BB, 3*HH, HH, hbc, HH, nullptr, whh, HH, bhh, gh, 3*HH);

        // GRU gates -> hid_new (+bf16 copy)
        gru_gate_k<<<(BB*HH)/256, 256>>>(gi, gh, hc, hn, hbn);

        // logits = hid_new @ outW^T + outb  (fp32 out)
        bgemm<0,0,0><<<dim3(VOCAB/128, 1), 256>>>(
            BB, VOCAB, HH, hbn, HH, nullptr, outw, HH, outb, logits, VOCAB);

        // log_softmax -> out[b, t, :]
        log_softmax_k<<<BB, 1024>>>(logits, out + (size_t)t*VOCAB);
    }
}

// round 4
// speedup vs baseline: 3.1241x; 1.0005x over previous
#include <cuda_runtime.h>
#include <cuda_bf16.h>
#include <math.h>
#include <stdint.h>

#define BB 128      // batch
#define LL 64       // encoder length
#define HH 512      // hidden
#define WORD 512
#define VOCAB 32000
#define TSTEPS 31   // T-1 decode steps

typedef __nv_bfloat16  bf16;
typedef __nv_bfloat162 bf162;

// ---------------- scratch (device globals; no allocation allowed) --------
// fp32
__device__ float g_encproj[BB*LL*HH];     // enc @ W1_enc^T (step-invariant)
__device__ float g_hidproj[BB*HH];
__device__ float g_e[BB*LL];
__device__ float g_ctx[BB*HH];
__device__ float g_gi[BB*3*HH];
__device__ float g_gh[BB*3*HH];
__device__ float g_hid0[BB*HH];
__device__ float g_hid1[BB*HH];
__device__ float g_logits[BB*VOCAB];
// bf16
__device__ bf16 g_encbf [BB*LL*HH];
__device__ bf16 g_w1l   [HH*HH];
__device__ bf16 g_w1h   [HH*HH];
__device__ bf16 g_w2    [HH*HH];
__device__ bf16 g_w3    [HH*HH];
__device__ bf16 g_wih   [3*HH*(WORD+HH)];
__device__ bf16 g_whh   [3*HH*HH];
__device__ bf16 g_outw  [VOCAB*HH];
__device__ bf16 g_a2bf  [BB*LL*HH];
__device__ bf16 g_a3bf  [BB*LL*HH];
__device__ bf16 g_xcatbf[BB*(WORD+HH)];
__device__ bf16 g_hbf0  [BB*HH];
__device__ bf16 g_hbf1  [BB*HH];

// ---------------- mma helpers --------------------------------------------
__device__ __forceinline__ uint32_t s2u(const void* p){
    return (uint32_t)__cvta_generic_to_shared(p);
}
__device__ __forceinline__ void ldsm4(uint32_t& a0,uint32_t& a1,uint32_t& a2,uint32_t& a3,uint32_t addr){
    asm volatile("ldmatrix.sync.aligned.m8n8.x4.shared.b16 {%0,%1,%2,%3},[%4];"
                 :"=r"(a0),"=r"(a1),"=r"(a2),"=r"(a3):"r"(addr));
}
__device__ __forceinline__ void ldsm2(uint32_t& b0,uint32_t& b1,uint32_t addr){
    asm volatile("ldmatrix.sync.aligned.m8n8.x2.shared.b16 {%0,%1},[%2];"
                 :"=r"(b0),"=r"(b1):"r"(addr));
}
__device__ __forceinline__ void mma16816(float* c,const uint32_t* a,const uint32_t* b){
    asm volatile("mma.sync.aligned.m16n8k16.row.col.f32.bf16.bf16.f32 "
                 "{%0,%1,%2,%3},{%4,%5,%6,%7},{%8,%9},{%0,%1,%2,%3};"
                 :"+f"(c[0]),"+f"(c[1]),"+f"(c[2]),"+f"(c[3])
                 :"r"(a[0]),"r"(a[1]),"r"(a[2]),"r"(a[3]),"r"(b[0]),"r"(b[1]));
}

// ---------------- bf16 tensor-core GEMM ----------------------------------
// C[M,N] = act(A[M,K] @ W[N,K]^T + bias)
// MODE_A: 0 = A is bf16[M,lda]; 1 = A = tanh(encproj_fp32[row,:] + hidproj[row>>6,:]) (fused)
// ACT:    1 = tanh epilogue
// OUT_BF: 1 = C bf16, 0 = C fp32
// Block tile 128x128xK, BK=32, 256 threads (8 warps as 2x4, warp tile 64x32).
#define BK 32
#define SPAD 8
template<int MODE_A,int ACT,int OUT_BF>
__global__ __launch_bounds__(256)
void bgemm(int M,int N,int K,
           const void* __restrict__ Aptr,int lda,
           const float* __restrict__ hidproj,
           const bf16* __restrict__ Wbf,int ldw,
           const float* __restrict__ bias,
           void* __restrict__ Cptr,int ldc)
{
    __shared__ bf16 As[128][BK+SPAD];
    __shared__ bf16 Ws[128][BK+SPAD];
    const int bm = blockIdx.y*128, bn = blockIdx.x*128;
    const int tid = threadIdx.x, lane = tid & 31, wid = tid >> 5;
    const int wm = wid & 1, wn = wid >> 1;

    float acc[4][4][4];
#pragma unroll
    for(int mi=0;mi<4;mi++)
#pragma unroll
        for(int ni=0;ni<4;ni++)
#pragma unroll
            for(int q=0;q<4;q++) acc[mi][ni][q]=0.f;

    for(int k0=0;k0<K;k0+=BK){
        // --- stage A tile (128 x 32) ---
        if(MODE_A==0){
            const bf16* Ab=(const bf16*)Aptr;
#pragma unroll
            for(int it=0;it<2;it++){
                int f=tid+it*256, r=f>>2, kq=(f&3)*8;
                *(uint4*)&As[r][kq] =
                    *(const uint4*)&Ab[(size_t)(bm+r)*lda + k0 + kq];
            }
        } else {
            const float* Af=(const float*)Aptr;
#pragma unroll
            for(int it=0;it<2;it++){
                int f=tid+it*256, r=f>>2, kq=(f&3)*8;
                int row=bm+r, b=row>>6;
                const float* ep=&Af[(size_t)row*lda + k0 + kq];
                const float* hp=&hidproj[b*HH + k0 + kq];
                float4 e0=*(const float4*)ep,      e1=*(const float4*)(ep+4);
                float4 h0=*(const float4*)hp,      h1=*(const float4*)(hp+4);
                union{ uint4 u; bf162 h[4]; } pk;
                pk.h[0]=__floats2bfloat162_rn(tanhf(e0.x+h0.x), tanhf(e0.y+h0.y));
                pk.h[1]=__floats2bfloat162_rn(tanhf(e0.z+h0.z), tanhf(e0.w+h0.w));
                pk.h[2]=__floats2bfloat162_rn(tanhf(e1.x+h1.x), tanhf(e1.y+h1.y));
                pk.h[3]=__floats2bfloat162_rn(tanhf(e1.z+h1.z), tanhf(e1.w+h1.w));
                *(uint4*)&As[r][kq] = pk.u;
            }
        }
        // --- stage W tile (128 x 32) ---
#pragma unroll
        for(int it=0;it<2;it++){
            int f=tid+it*256, r=f>>2, kq=(f&3)*8;
            *(uint4*)&Ws[r][kq] =
                *(const uint4*)&Wbf[(size_t)(bn+r)*ldw + k0 + kq];
        }
        __syncthreads();

#pragma unroll
        for(int ks=0;ks<2;ks++){
            uint32_t af[4][4], bw[4][2];
#pragma unroll
            for(int mi=0;mi<4;mi++)
                ldsm4(af[mi][0],af[mi][1],af[mi][2],af[mi][3],
                      s2u(&As[wm*64+mi*16 + (lane&15)][ks*16 + (lane>>4)*8]));
#pragma unroll
            for(int ni=0;ni<4;ni++)
                ldsm2(bw[ni][0],bw[ni][1],
                      s2u(&Ws[wn*32+ni*8 + (lane&7)][ks*16 + ((lane>>3)&1)*8]));
#pragma unroll
            for(int mi=0;mi<4;mi++)
#pragma unroll
                for(int ni=0;ni<4;ni++) mma16816(acc[mi][ni],af[mi],bw[ni]);
        }
        __syncthreads();
    }

    // --- epilogue ---
#pragma unroll
    for(int mi=0;mi<4;mi++){
#pragma unroll
        for(int ni=0;ni<4;ni++){
            int row = bm + wm*64 + mi*16 + (lane>>2);
            int col = bn + wn*32 + ni*8  + (lane&3)*2;
#pragma unroll
            for(int half=0;half<2;half++){
                int r2 = row + half*8;
                float v0 = acc[mi][ni][2*half+0];
                float v1 = acc[mi][ni][2*half+1];
                if(bias){ v0 += bias[col]; v1 += bias[col+1]; }
                if(ACT){ v0 = tanhf(v0); v1 = tanhf(v1); }
                if(OUT_BF){
                    ((bf162*)Cptr)[((size_t)r2*ldc + col)>>1] = __floats2bfloat162_rn(v0,v1);
                } else {
                    *(float2*)&((float*)Cptr)[(size_t)r2*ldc + col] = make_float2(v0,v1);
                }
            }
        }
    }
}

// ---------------- small helpers ------------------------------------------
__global__ void copy_f32(const float* __restrict__ src, float* __restrict__ dst, int n){
    int i = blockIdx.x*256 + threadIdx.x;
    if (i < n) dst[i] = src[i];
}
// fp32 (strided 2-D) -> bf16 (dense)
__global__ void cvt2d_k(const float* __restrict__ src, int lds, int cols,
                        bf16* __restrict__ dst, long long n){
    long long i = (long long)blockIdx.x*256 + threadIdx.x;
    if (i >= n) return;
    long long r = i / cols; int c = (int)(i - r*cols);
    dst[i] = __float2bfloat16(src[r*(long long)lds + c]);
}

// e[row] = dot(a3[row,:], v)   (one warp per row; a3 bf16)
__global__ void att_score_k(const bf16* __restrict__ a3,
                            const float* __restrict__ v,
                            float* __restrict__ e){
    int row = blockIdx.x*8 + threadIdx.y;
    const bf16* p = a3 + (size_t)row*HH;
    float s = 0.f;
    for (int h = threadIdx.x; h < HH; h += 32) s = fmaf(__bfloat162float(p[h]), v[h], s);
#pragma unroll
    for (int o=16;o;o>>=1) s += __shfl_xor_sync(0xffffffffu, s, o);
    if (threadIdx.x==0) e[row] = s;
}

// softmax over L then ctx[b,h] = sum_l alpha[l]*enc[b,l,h]
__global__ void softmax_ctx_k(const float* __restrict__ e,
                              const float* __restrict__ enc,
                              float* __restrict__ ctx){
    int b = blockIdx.x, tid = threadIdx.x;
    __shared__ float alpha[LL];
    if (tid==0) {
        float m = -INFINITY;
        for (int l=0;l<LL;l++) m = fmaxf(m, e[b*LL+l]);
        float s = 0.f;
        for (int l=0;l<LL;l++){ float x = expf(e[b*LL+l]-m); alpha[l]=x; s+=x; }
        float inv = 1.f/s;
        for (int l=0;l<LL;l++) alpha[l]*=inv;
    }
    __syncthreads();
    const float* eb = enc + (size_t)b*LL*HH;
    for (int h=tid; h<HH; h+=blockDim.x) {
        float s = 0.f;
#pragma unroll 8
        for (int l=0;l<LL;l++) s = fmaf(alpha[l], eb[l*HH+h], s);
        ctx[b*HH+h] = s;
    }
}

// xcat(bf16) = [embed_W[targets[b,t]], ctx[b]]   (targets int32)
__global__ void build_xcat_k(const int* __restrict__ targets, int t,
                             const float* __restrict__ embed,
                             const float* __restrict__ ctx,
                             bf16* __restrict__ xcat){
    int b = blockIdx.x, tid = threadIdx.x;
    int tok = targets[b*32 + t];
    if (tok < 0) tok = 0;
    if (tok >= VOCAB) tok = VOCAB-1;
    const float* er = embed + (size_t)tok*WORD;
    for (int h=tid; h<WORD+HH; h+=blockDim.x){
        float v = (h<WORD) ? er[h] : ctx[b*HH + (h-WORD)];
        xcat[b*(WORD+HH)+h] = __float2bfloat16(v);
    }
}

// GRU gates -> hid_new (fp32 + bf16 copy)
__global__ void gru_gate_k(const float* __restrict__ gi, const float* __restrict__ gh,
                           const float* __restrict__ hid,
                           float* __restrict__ hidn, bf16* __restrict__ hidnbf){
    int idx = blockIdx.x*256 + threadIdx.x;   // BB*HH
    int b = idx >> 9, h = idx & (HH-1);
    const float* gib = gi + (size_t)b*3*HH;
    const float* ghb = gh + (size_t)b*3*HH;
    float r = 1.f/(1.f+expf(-(gib[h]        + ghb[h])));
    float z = 1.f/(1.f+expf(-(gib[HH+h]     + ghb[HH+h])));
    float n = tanhf(gib[2*HH+h] + r*ghb[2*HH+h]);
    float hv = (1.f-z)*n + z*hid[idx];
    hidn[idx] = hv;
    hidnbf[idx] = __float2bfloat16(hv);
}

// log_softmax over VOCAB -> out (out already offset by t; per-b stride = TSTEPS*VOCAB)
__global__ __launch_bounds__(1024)
void log_softmax_k(const float* __restrict__ logits, float* __restrict__ out){
    int b = blockIdx.x, tid = threadIdx.x;
    const float* p = logits + (size_t)b*VOCAB;
    float* o = out + (size_t)b*TSTEPS*VOCAB;
    __shared__ float red[32];
    float m = -INFINITY;
    for (int v=tid; v<VOCAB; v+=1024) m = fmaxf(m, p[v]);
#pragma unroll
    for (int x=16;x;x>>=1) m = fmaxf(m, __shfl_xor_sync(0xffffffffu, m, x));
    if ((tid&31)==0) red[tid>>5] = m;
    __syncthreads();
    if (tid<32){ float mm = red[tid];
#pragma unroll
        for (int x=16;x;x>>=1) mm = fmaxf(mm, __shfl_xor_sync(0xffffffffu, mm, x));
        red[tid]=mm; }
    __syncthreads();
    m = red[0];
    __syncthreads();
    float s = 0.f;
    for (int v=tid; v<VOCAB; v+=1024) s += expf(p[v]-m);
#pragma unroll
    for (int x=16;x;x>>=1) s += __shfl_xor_sync(0xffffffffu, s, x);
    if ((tid&31)==0) red[tid>>5] = s;
    __syncthreads();
    if (tid<32){ float ss = red[tid];
#pragma unroll
        for (int x=16;x;x>>=1) ss += __shfl_xor_sync(0xffffffffu, ss, x);
        red[tid]=ss; }
    __syncthreads();
    float lse = m + logf(red[0]);
    for (int v=tid; v<VOCAB; v+=1024) o[v] = p[v] - lse;
}

// ---------------- host side ----------------------------------------------
static void* symaddr_checked(const void* sym){
    void* p = nullptr;
    if (cudaGetSymbolAddress(&p, sym) != cudaSuccess) p = nullptr;
    return p;
}

extern "C" void kernel_launch(void* const* d_in, const int* in_sizes, int n_in,
                              void* d_out, int out_size) {
    const float* enc   = (const float*)d_in[0];   // (128,64,512)
    const float* h0    = (const float*)d_in[1];   // (1,128,512)
    const int*   tgt   = (const int*)d_in[2];     // (128,32) int32
    const float* embed = (const float*)d_in[3];
    const float* W1    = (const float*)d_in[4];   // (512,1024)
    const float* b1    = (const float*)d_in[5];
    const float* W2    = (const float*)d_in[6];
    const float* b2    = (const float*)d_in[7];
    const float* W3    = (const float*)d_in[8];
    const float* b3    = (const float*)d_in[9];
    const float* attv  = (const float*)d_in[10];
    const float* Wih   = (const float*)d_in[11];  // (1536,1024)
    const float* Whh   = (const float*)d_in[12];  // (1536,512)
    const float* bih   = (const float*)d_in[13];
    const float* bhh   = (const float*)d_in[14];
    const float* outW  = (const float*)d_in[15];  // (32000,512)
    const float* outb  = (const float*)d_in[16];
    float* out = (float*)d_out;

    static float *encproj=nullptr,*hidproj,*ebuf,*ctx,*gi,*gh,*hidA,*hidB,*logits;
    static bf16  *encbf,*w1l,*w1h,*w2,*w3,*wih,*whh,*outw,*a2bf,*a3bf,*xcatbf,*hbfA,*hbfB;
    if (!encproj) {
        encproj=(float*)symaddr_checked(g_encproj);
        hidproj=(float*)symaddr_checked(g_hidproj);
        ebuf   =(float*)symaddr_checked(g_e);
        ctx    =(float*)symaddr_checked(g_ctx);
        gi     =(float*)symaddr_checked(g_gi);
        gh     =(float*)symaddr_checked(g_gh);
        hidA   =(float*)symaddr_checked(g_hid0);
        hidB   =(float*)symaddr_checked(g_hid1);
        logits =(float*)symaddr_checked(g_logits);
        encbf  =(bf16*)symaddr_checked(g_encbf);
        w1l    =(bf16*)symaddr_checked(g_w1l);
        w1h    =(bf16*)symaddr_checked(g_w1h);
        w2     =(bf16*)symaddr_checked(g_w2);
        w3     =(bf16*)symaddr_checked(g_w3);
        wih    =(bf16*)symaddr_checked(g_wih);
        whh    =(bf16*)symaddr_checked(g_whh);
        outw   =(bf16*)symaddr_checked(g_outw);
        a2bf   =(bf16*)symaddr_checked(g_a2bf);
        a3bf   =(bf16*)symaddr_checked(g_a3bf);
        xcatbf =(bf16*)symaddr_checked(g_xcatbf);
        hbfA   =(bf16*)symaddr_checked(g_hbf0);
        hbfB   =(bf16*)symaddr_checked(g_hbf1);
    }
    float* hid[2] = { hidA, hidB };
    bf16*  hbf[2] = { hbfA, hbfB };

    const int M = BB*LL;  // 8192
    auto blks = [](long long n){ return (int)((n + 255)/256); };

    // ---- one-time per launch: conversions + invariant GEMM ----
    copy_f32<<<blks(BB*HH),256>>>(h0, hid[0], BB*HH);
    cvt2d_k<<<blks(BB*HH),256>>>(h0, HH, HH, hbf[0], (long long)BB*HH);
    cvt2d_k<<<blks((long long)M*HH),256>>>(enc, HH, HH, encbf, (long long)M*HH);
    cvt2d_k<<<blks(HH*HH),256>>>(W1,      2*HH, HH, w1l, (long long)HH*HH);
    cvt2d_k<<<blks(HH*HH),256>>>(W1+HH,   2*HH, HH, w1h, (long long)HH*HH);
    cvt2d_k<<<blks(HH*HH),256>>>(W2,      HH,   HH, w2,  (long long)HH*HH);
    cvt2d_k<<<blks(HH*HH),256>>>(W3,      HH,   HH, w3,  (long long)HH*HH);
    cvt2d_k<<<blks((long long)3*HH*(WORD+HH)),256>>>(Wih, WORD+HH, WORD+HH, wih, (long long)3*HH*(WORD+HH));
    cvt2d_k<<<blks((long long)3*HH*HH),256>>>(Whh, HH, HH, whh, (long long)3*HH*HH);
    cvt2d_k<<<blks((long long)VOCAB*HH),256>>>(outW, HH, HH, outw, (long long)VOCAB*HH);

    // encproj = enc @ W1_enc^T  (no bias/act; fp32 out)
    bgemm<0,0,0><<<dim3(HH/128, M/128), 256>>>(
        M, HH, HH, encbf, HH, nullptr, w1l, HH, nullptr, encproj, HH);

    for (int t = 0; t < TSTEPS; t++) {
        const float* hc  = hid[t & 1];
        float*       hn  = hid[(t+1) & 1];
        const bf16*  hbc = hbf[t & 1];
        bf16*        hbn = hbf[(t+1) & 1];

        // hidproj = hid @ W1_hid^T + b1   (fp32 out)
        bgemm<0,0,0><<<dim3(HH/128, 1), 256>>>(
            BB, HH, HH, hbc, HH, nullptr, w1h, HH, b1, hidproj, HH);

        // a2 = tanh( tanh(encproj + hidproj) @ W2^T + b2 )   (fused A, bf16 out)
        bgemm<1,1,1><<<dim3(HH/128, M/128), 256>>>(
            M, HH, HH, encproj, HH, hidproj, w2, HH, b2, a2bf, HH);

        // a3 = tanh(a2 @ W3^T + b3)   (bf16 out)
        bgemm<0,1,1><<<dim3(HH/128, M/128), 256>>>(
            M, HH, HH, a2bf, HH, nullptr, w3, HH, b3, a3bf, HH);

        // e = a3 . v ; softmax + context ; xcat
        att_score_k<<<M/8, dim3(32,8)>>>(a3bf, attv, ebuf);
        softmax_ctx_k<<<BB, 256>>>(ebuf, enc, ctx);
        build_xcat_k<<<BB, 256>>>(tgt, t, embed, ctx, xcatbf);

        // gi = xcat @ Wih^T + bih ; gh = hid @ Whh^T + bhh   (fp32 out)
        bgemm<0,0,0><<<dim3(3*HH/128, 1), 256>>>(
            BB, 3*HH, WORD+HH, xcatbf, WORD+HH, nullptr, wih, WORD+HH, bih, gi, 3*HH);
        bgemm<0,0,0><<<dim3(3*HH/128, 1), 256>>>(
            BB, 3*HH, HH, hbc, HH, nullptr, whh, HH, bhh, gh, 3*HH);

        // GRU gates -> hid_new (+bf16 copy)
        gru_gate_k<<<(BB*HH)/256, 256>>>(gi, gh, hc, hn, hbn);

        // logits = hid_new @ outW^T + outb  (fp32 out)
        bgemm<0,0,0><<<dim3(VOCAB/128, 1), 256>>>(
            BB, VOCAB, HH, hbn, HH, nullptr, outw, HH, outb, logits, VOCAB);

        // log_softmax -> out[b, t, :]
        log_softmax_k<<<BB, 1024>>>(logits, out + (size_t)t*VOCAB);
    }
}

// round 5
// speedup vs baseline: 3.1274x; 1.0010x over previous
#include <cuda_runtime.h>
#include <cuda_bf16.h>
#include <math.h>
#include <stdint.h>

#define BB 128      // batch
#define LL 64       // encoder length
#define HH 512      // hidden
#define WORD 512
#define VOCAB 32000
#define TSTEPS 31   // T-1 decode steps

typedef __nv_bfloat16  bf16;
typedef __nv_bfloat162 bf162;

// ---------------- scratch (device globals; no allocation allowed) --------
// fp32
__device__ float g_encproj[BB*LL*HH];     // enc @ W1_enc^T (step-invariant)
__device__ float g_hidproj[BB*HH];
__device__ float g_e[BB*LL];
__device__ float g_ctx[BB*HH];
__device__ float g_gi[BB*3*HH];
__device__ float g_gh[BB*3*HH];
__device__ float g_hid0[BB*HH];
__device__ float g_hid1[BB*HH];
__device__ float g_logits[BB*VOCAB];
// bf16
__device__ bf16 g_encbf [BB*LL*HH];
__device__ bf16 g_w1l   [HH*HH];
__device__ bf16 g_w1h   [HH*HH];
__device__ bf16 g_w2    [HH*HH];
__device__ bf16 g_w3    [HH*HH];
__device__ bf16 g_wih   [3*HH*(WORD+HH)];
__device__ bf16 g_whh   [3*HH*HH];
__device__ bf16 g_outw  [VOCAB*HH];
__device__ bf16 g_a2bf  [BB*LL*HH];
__device__ bf16 g_a3bf  [BB*LL*HH];
__device__ bf16 g_xcatbf[BB*(WORD+HH)];
__device__ bf16 g_hbf0  [BB*HH];
__device__ bf16 g_hbf1  [BB*HH];

// ---------------- mma helpers --------------------------------------------
__device__ __forceinline__ uint32_t s2u(const void* p){
    return (uint32_t)__cvta_generic_to_shared(p);
}
__device__ __forceinline__ void ldsm4(uint32_t& a0,uint32_t& a1,uint32_t& a2,uint32_t& a3,uint32_t addr){
    asm volatile("ldmatrix.sync.aligned.m8n8.x4.shared.b16 {%0,%1,%2,%3},[%4];"
                 :"=r"(a0),"=r"(a1),"=r"(a2),"=r"(a3):"r"(addr));
}
__device__ __forceinline__ void ldsm2(uint32_t& b0,uint32_t& b1,uint32_t addr){
    asm volatile("ldmatrix.sync.aligned.m8n8.x2.shared.b16 {%0,%1},[%2];"
                 :"=r"(b0),"=r"(b1):"r"(addr));
}
__device__ __forceinline__ void mma16816(float* c,const uint32_t* a,const uint32_t* b){
    asm volatile("mma.sync.aligned.m16n8k16.row.col.f32.bf16.bf16.f32 "
                 "{%0,%1,%2,%3},{%4,%5,%6,%7},{%8,%9},{%0,%1,%2,%3};"
                 :"+f"(c[0]),"+f"(c[1]),"+f"(c[2]),"+f"(c[3])
                 :"r"(a[0]),"r"(a[1]),"r"(a[2]),"r"(a[3]),"r"(b[0]),"r"(b[1]));
}

// ---------------- bf16 tensor-core GEMM ----------------------------------
// C[M,N] = act(A[M,K] @ W[N,K]^T + bias)
// MODE_A: 0 = A is bf16[M,lda]; 1 = A = tanh(encproj_fp32[row,:] + hidproj[row>>6,:]) (fused)
// ACT:    1 = tanh epilogue
// OUT_BF: 1 = C bf16, 0 = C fp32
// Block tile 128x128xK, BK=32, 256 threads (8 warps as 2x4, warp tile 64x32).
#define BK 32
#define SPAD 8
template<int MODE_A,int ACT,int OUT_BF>
__global__ __launch_bounds__(256)
void bgemm(int M,int N,int K,
           const void* __restrict__ Aptr,int lda,
           const float* __restrict__ hidproj,
           const bf16* __restrict__ Wbf,int ldw,
           const float* __restrict__ bias,
           void* __restrict__ Cptr,int ldc)
{
    __shared__ bf16 As[128][BK+SPAD];
    __shared__ bf16 Ws[128][BK+SPAD];
    const int bm = blockIdx.y*128, bn = blockIdx.x*128;
    const int tid = threadIdx.x, lane = tid & 31, wid = tid >> 5;
    const int wm = wid & 1, wn = wid >> 1;

    float acc[4][4][4];
#pragma unroll
    for(int mi=0;mi<4;mi++)
#pragma unroll
        for(int ni=0;ni<4;ni++)
#pragma unroll
            for(int q=0;q<4;q++) acc[mi][ni][q]=0.f;

    for(int k0=0;k0<K;k0+=BK){
        // --- stage A tile (128 x 32) ---
        if(MODE_A==0){
            const bf16* Ab=(const bf16*)Aptr;
#pragma unroll
            for(int it=0;it<2;it++){
                int f=tid+it*256, r=f>>2, kq=(f&3)*8;
                *(uint4*)&As[r][kq] =
                    *(const uint4*)&Ab[(size_t)(bm+r)*lda + k0 + kq];
            }
        } else {
            const float* Af=(const float*)Aptr;
#pragma unroll
            for(int it=0;it<2;it++){
                int f=tid+it*256, r=f>>2, kq=(f&3)*8;
                int row=bm+r, b=row>>6;
                const float* ep=&Af[(size_t)row*lda + k0 + kq];
                const float* hp=&hidproj[b*HH + k0 + kq];
                float4 e0=*(const float4*)ep,      e1=*(const float4*)(ep+4);
                float4 h0=*(const float4*)hp,      h1=*(const float4*)(hp+4);
                union{ uint4 u; bf162 h[4]; } pk;
                pk.h[0]=__floats2bfloat162_rn(tanhf(e0.x+h0.x), tanhf(e0.y+h0.y));
                pk.h[1]=__floats2bfloat162_rn(tanhf(e0.z+h0.z), tanhf(e0.w+h0.w));
                pk.h[2]=__floats2bfloat162_rn(tanhf(e1.x+h1.x), tanhf(e1.y+h1.y));
                pk.h[3]=__floats2bfloat162_rn(tanhf(e1.z+h1.z), tanhf(e1.w+h1.w));
                *(uint4*)&As[r][kq] = pk.u;
            }
        }
        // --- stage W tile (128 x 32) ---
#pragma unroll
        for(int it=0;it<2;it++){
            int f=tid+it*256, r=f>>2, kq=(f&3)*8;
            *(uint4*)&Ws[r][kq] =
                *(const uint4*)&Wbf[(size_t)(bn+r)*ldw + k0 + kq];
        }
        __syncthreads();

#pragma unroll
        for(int ks=0;ks<2;ks++){
            uint32_t af[4][4], bw[4][2];
#pragma unroll
            for(int mi=0;mi<4;mi++)
                ldsm4(af[mi][0],af[mi][1],af[mi][2],af[mi][3],
                      s2u(&As[wm*64+mi*16 + (lane&15)][ks*16 + (lane>>4)*8]));
#pragma unroll
            for(int ni=0;ni<4;ni++)
                ldsm2(bw[ni][0],bw[ni][1],
                      s2u(&Ws[wn*32+ni*8 + (lane&7)][ks*16 + ((lane>>3)&1)*8]));
#pragma unroll
            for(int mi=0;mi<4;mi++)
#pragma unroll
                for(int ni=0;ni<4;ni++) mma16816(acc[mi][ni],af[mi],bw[ni]);
        }
        __syncthreads();
    }

    // --- epilogue ---
#pragma unroll
    for(int mi=0;mi<4;mi++){
#pragma unroll
        for(int ni=0;ni<4;ni++){
            int row = bm + wm*64 + mi*16 + (lane>>2);
            int col = bn + wn*32 + ni*8  + (lane&3)*2;
#pragma unroll
            for(int half=0;half<2;half++){
                int r2 = row + half*8;
                float v0 = acc[mi][ni][2*half+0];
                float v1 = acc[mi][ni][2*half+1];
                if(bias){ v0 += bias[col]; v1 += bias[col+1]; }
                if(ACT){ v0 = tanhf(v0); v1 = tanhf(v1); }
                if(OUT_BF){
                    ((bf162*)Cptr)[((size_t)r2*ldc + col)>>1] = __floats2bfloat162_rn(v0,v1);
                } else {
                    *(float2*)&((float*)Cptr)[(size_t)r2*ldc + col] = make_float2(v0,v1);
                }
            }
        }
    }
}

// ---------------- small helpers ------------------------------------------
__global__ void copy_f32(const float* __restrict__ src, float* __restrict__ dst, int n){
    int i = blockIdx.x*256 + threadIdx.x;
    if (i < n) dst[i] = src[i];
}
// fp32 (strided 2-D) -> bf16 (dense)
__global__ void cvt2d_k(const float* __restrict__ src, int lds, int cols,
                        bf16* __restrict__ dst, long long n){
    long long i = (long long)blockIdx.x*256 + threadIdx.x;
    if (i >= n) return;
    long long r = i / cols; int c = (int)(i - r*cols);
    dst[i] = __float2bfloat16(src[r*(long long)lds + c]);
}

// e[row] = dot(a3[row,:], v)   (one warp per row; a3 bf16)
__global__ void att_score_k(const bf16* __restrict__ a3,
                            const float* __restrict__ v,
                            float* __restrict__ e){
    int row = blockIdx.x*8 + threadIdx.y;
    const bf16* p = a3 + (size_t)row*HH;
    float s = 0.f;
    for (int h = threadIdx.x; h < HH; h += 32) s = fmaf(__bfloat162float(p[h]), v[h], s);
#pragma unroll
    for (int o=16;o;o>>=1) s += __shfl_xor_sync(0xffffffffu, s, o);
    if (threadIdx.x==0) e[row] = s;
}

// softmax over L then ctx[b,h] = sum_l alpha[l]*enc[b,l,h]
__global__ void softmax_ctx_k(const float* __restrict__ e,
                              const float* __restrict__ enc,
                              float* __restrict__ ctx){
    int b = blockIdx.x, tid = threadIdx.x;
    __shared__ float alpha[LL];
    if (tid==0) {
        float m = -INFINITY;
        for (int l=0;l<LL;l++) m = fmaxf(m, e[b*LL+l]);
        float s = 0.f;
        for (int l=0;l<LL;l++){ float x = expf(e[b*LL+l]-m); alpha[l]=x; s+=x; }
        float inv = 1.f/s;
        for (int l=0;l<LL;l++) alpha[l]*=inv;
    }
    __syncthreads();
    const float* eb = enc + (size_t)b*LL*HH;
    for (int h=tid; h<HH; h+=blockDim.x) {
        float s = 0.f;
#pragma unroll 8
        for (int l=0;l<LL;l++) s = fmaf(alpha[l], eb[l*HH+h], s);
        ctx[b*HH+h] = s;
    }
}

// xcat(bf16) = [embed_W[targets[b,t]], ctx[b]]   (targets int32)
__global__ void build_xcat_k(const int* __restrict__ targets, int t,
                             const float* __restrict__ embed,
                             const float* __restrict__ ctx,
                             bf16* __restrict__ xcat){
    int b = blockIdx.x, tid = threadIdx.x;
    int tok = targets[b*32 + t];
    if (tok < 0) tok = 0;
    if (tok >= VOCAB) tok = VOCAB-1;
    const float* er = embed + (size_t)tok*WORD;
    for (int h=tid; h<WORD+HH; h+=blockDim.x){
        float v = (h<WORD) ? er[h] : ctx[b*HH + (h-WORD)];
        xcat[b*(WORD+HH)+h] = __float2bfloat16(v);
    }
}

// GRU gates -> hid_new (fp32 + bf16 copy)
__global__ void gru_gate_k(const float* __restrict__ gi, const float* __restrict__ gh,
                           const float* __restrict__ hid,
                           float* __restrict__ hidn, bf16* __restrict__ hidnbf){
    int idx = blockIdx.x*256 + threadIdx.x;   // BB*HH
    int b = idx >> 9, h = idx & (HH-1);
    const float* gib = gi + (size_t)b*3*HH;
    const float* ghb = gh + (size_t)b*3*HH;
    float r = 1.f/(1.f+expf(-(gib[h]        + ghb[h])));
    float z = 1.f/(1.f+expf(-(gib[HH+h]     + ghb[HH+h])));
    float n = tanhf(gib[2*HH+h] + r*ghb[2*HH+h]);
    float hv = (1.f-z)*n + z*hid[idx];
    hidn[idx] = hv;
    hidnbf[idx] = __float2bfloat16(hv);
}

// log_softmax over VOCAB -> out (out already offset by t; per-b stride = TSTEPS*VOCAB)
__global__ __launch_bounds__(1024)
void log_softmax_k(const float* __restrict__ logits, float* __restrict__ out){
    int b = blockIdx.x, tid = threadIdx.x;
    const float* p = logits + (size_t)b*VOCAB;
    float* o = out + (size_t)b*TSTEPS*VOCAB;
    __shared__ float red[32];
    float m = -INFINITY;
    for (int v=tid; v<VOCAB; v+=1024) m = fmaxf(m, p[v]);
#pragma unroll
    for (int x=16;x;x>>=1) m = fmaxf(m, __shfl_xor_sync(0xffffffffu, m, x));
    if ((tid&31)==0) red[tid>>5] = m;
    __syncthreads();
    if (tid<32){ float mm = red[tid];
#pragma unroll
        for (int x=16;x;x>>=1) mm = fmaxf(mm, __shfl_xor_sync(0xffffffffu, mm, x));
        red[tid]=mm; }
    __syncthreads();
    m = red[0];
    __syncthreads();
    float s = 0.f;
    for (int v=tid; v<VOCAB; v+=1024) s += expf(p[v]-m);
#pragma unroll
    for (int x=16;x;x>>=1) s += __shfl_xor_sync(0xffffffffu, s, x);
    if ((tid&31)==0) red[tid>>5] = s;
    __syncthreads();
    if (tid<32){ float ss = red[tid];
#pragma unroll
        for (int x=16;x;x>>=1) ss += __shfl_xor_sync(0xffffffffu, ss, x);
        red[tid]=ss; }
    __syncthreads();
    float lse = m + logf(red[0]);
    for (int v=tid; v<VOCAB; v+=1024) o[v] = p[v] - lse;
}

// ---------------- host side ----------------------------------------------
static void* symaddr_checked(const void* sym){
    void* p = nullptr;
    if (cudaGetSymbolAddress(&p, sym) != cudaSuccess) p = nullptr;
    return p;
}

extern "C" void kernel_launch(void* const* d_in, const int* in_sizes, int n_in,
                              void* d_out, int out_size) {
    const float* enc   = (const float*)d_in[0];   // (128,64,512)
    const float* h0    = (const float*)d_in[1];   // (1,128,512)
    const int*   tgt   = (const int*)d_in[2];     // (128,32) int32
    const float* embed = (const float*)d_in[3];
    const float* W1    = (const float*)d_in[4];   // (512,1024)
    const float* b1    = (const float*)d_in[5];
    const float* W2    = (const float*)d_in[6];
    const float* b2    = (const float*)d_in[7];
    const float* W3    = (const float*)d_in[8];
    const float* b3    = (const float*)d_in[9];
    const float* attv  = (const float*)d_in[10];
    const float* Wih   = (const float*)d_in[11];  // (1536,1024)
    const float* Whh   = (const float*)d_in[12];  // (1536,512)
    const float* bih   = (const float*)d_in[13];
    const float* bhh   = (const float*)d_in[14];
    const float* outW  = (const float*)d_in[15];  // (32000,512)
    const float* outb  = (const float*)d_in[16];
    float* out = (float*)d_out;

    static float *encproj=nullptr,*hidproj,*ebuf,*ctx,*gi,*gh,*hidA,*hidB,*logits;
    static bf16  *encbf,*w1l,*w1h,*w2,*w3,*wih,*whh,*outw,*a2bf,*a3bf,*xcatbf,*hbfA,*hbfB;
    if (!encproj) {
        encproj=(float*)symaddr_checked(g_encproj);
        hidproj=(float*)symaddr_checked(g_hidproj);
        ebuf   =(float*)symaddr_checked(g_e);
        ctx    =(float*)symaddr_checked(g_ctx);
        gi     =(float*)symaddr_checked(g_gi);
        gh     =(float*)symaddr_checked(g_gh);
        hidA   =(float*)symaddr_checked(g_hid0);
        hidB   =(float*)symaddr_checked(g_hid1);
        logits =(float*)symaddr_checked(g_logits);
        encbf  =(bf16*)symaddr_checked(g_encbf);
        w1l    =(bf16*)symaddr_checked(g_w1l);
        w1h    =(bf16*)symaddr_checked(g_w1h);
        w2     =(bf16*)symaddr_checked(g_w2);
        w3     =(bf16*)symaddr_checked(g_w3);
        wih    =(bf16*)symaddr_checked(g_wih);
        whh    =(bf16*)symaddr_checked(g_whh);
        outw   =(bf16*)symaddr_checked(g_outw);
        a2bf   =(bf16*)symaddr_checked(g_a2bf);
        a3bf   =(bf16*)symaddr_checked(g_a3bf);
        xcatbf =(bf16*)symaddr_checked(g_xcatbf);
        hbfA   =(bf16*)symaddr_checked(g_hbf0);
        hbfB   =(bf16*)symaddr_checked(g_hbf1);
    }
    float* hid[2] = { hidA, hidB };
    bf16*  hbf[2] = { hbfA, hbfB };

    const int M = BB*LL;  // 8192
    auto blks = [](long long n){ return (int)((n + 255)/256); };

    // ---- one-time per launch: conversions + invariant GEMM ----
    copy_f32<<<blks(BB*HH),256>>>(h0, hid[0], BB*HH);
    cvt2d_k<<<blks(BB*HH),256>>>(h0, HH, HH, hbf[0], (long long)BB*HH);
    cvt2d_k<<<blks((long long)M*HH),256>>>(enc, HH, HH, encbf, (long long)M*HH);
    cvt2d_k<<<blks(HH*HH),256>>>(W1,      2*HH, HH, w1l, (long long)HH*HH);
    cvt2d_k<<<blks(HH*HH),256>>>(W1+HH,   2*HH, HH, w1h, (long long)HH*HH);
    cvt2d_k<<<blks(HH*HH),256>>>(W2,      HH,   HH, w2,  (long long)HH*HH);
    cvt2d_k<<<blks(HH*HH),256>>>(W3,      HH,   HH, w3,  (long long)HH*HH);
    cvt2d_k<<<blks((long long)3*HH*(WORD+HH)),256>>>(Wih, WORD+HH, WORD+HH, wih, (long long)3*HH*(WORD+HH));
    cvt2d_k<<<blks((long long)3*HH*HH),256>>>(Whh, HH, HH, whh, (long long)3*HH*HH);
    cvt2d_k<<<blks((long long)VOCAB*HH),256>>>(outW, HH, HH, outw, (long long)VOCAB*HH);

    // encproj = enc @ W1_enc^T  (no bias/act; fp32 out)
    bgemm<0,0,0><<<dim3(HH/128, M/128), 256>>>(
        M, HH, HH, encbf, HH, nullptr, w1l, HH, nullptr, encproj, HH);

    for (int t = 0; t < TSTEPS; t++) {
        const float* hc  = hid[t & 1];
        float*       hn  = hid[(t+1) & 1];
        const bf16*  hbc = hbf[t & 1];
        bf16*        hbn = hbf[(t+1) & 1];

        // hidproj = hid @ W1_hid^T + b1   (fp32 out)
        bgemm<0,0,0><<<dim3(HH/128, 1), 256>>>(
            BB, HH, HH, hbc, HH, nullptr, w1h, HH, b1, hidproj, HH);

        // a2 = tanh( tanh(encproj + hidproj) @ W2^T + b2 )   (fused A, bf16 out)
        bgemm<1,1,1><<<dim3(HH/128, M/128), 256>>>(
            M, HH, HH, encproj, HH, hidproj, w2, HH, b2, a2bf, HH);

        // a3 = tanh(a2 @ W3^T + b3)   (bf16 out)
        bgemm<0,1,1><<<dim3(HH/128, M/128), 256>>>(
            M, HH, HH, a2bf, HH, nullptr, w3, HH, b3, a3bf, HH);

        // e = a3 . v ; softmax + context ; xcat
        att_score_k<<<M/8, dim3(32,8)>>>(a3bf, attv, ebuf);
        softmax_ctx_k<<<BB, 256>>>(ebuf, enc, ctx);
        build_xcat_k<<<BB, 256>>>(tgt, t, embed, ctx, xcatbf);

        // gi = xcat @ Wih^T + bih ; gh = hid @ Whh^T + bhh   (fp32 out)
        bgemm<0,0,0><<<dim3(3*HH/128, 1), 256>>>(
            BB, 3*HH, WORD+HH, xcatbf, WORD+HH, nullptr, wih, WORD+HH, bih, gi, 3*HH);
        bgemm<0,0,0><<<dim3(3*HH/128, 1), 256>>>(
            BB, 3*HH, HH, hbc, HH, nullptr, whh, HH, bhh, gh, 3*HH);

        // GRU gates -> hid_new (+bf16 copy)
        gru_gate_k<<<(BB*HH)/256, 256>>>(gi, gh, hc, hn, hbn);

        // logits = hid_new @ outW^T + outb  (fp32 out)
        bgemm<0,0,0><<<dim3(VOCAB/128, 1), 256>>>(
            BB, VOCAB, HH, hbn, HH, nullptr, outw, HH, outb, logits, VOCAB);

        // log_softmax -> out[b, t, :]
        log_softmax_k<<<BB, 1024>>>(logits, out + (size_t)t*VOCAB);
    }
}